// round 11
// baseline (speedup 1.0000x reference)
#include <cuda_runtime.h>
#include <math.h>

#define Hh 512
#define Ww 512
#define NPIX (512*512)
#define KK 50
#define BB 16
#define SLIC_ITERS 10

// scratch (static device arrays; no dynamic allocation allowed)
__device__ double        g_accum[BB][KK][6];     // [0..4]=feat sums, [5]=count
__device__ float         g_centers[BB][KK][5];
__device__ unsigned char g_labels[BB][NPIX];
__device__ double        g_colorsum[BB][3];

__device__ __forceinline__ float ratio_f() {
    return (float)(10.0 / sqrt((double)NPIX / (double)KK));
}

// ---------------------------------------------------------------------------
// init: zero accumulators + grid-initialized centers (first 50 of 8x8 grid)
// ---------------------------------------------------------------------------
__global__ void init_kernel(const float* __restrict__ x) {
    int b = blockIdx.x;
    int tid = threadIdx.x;
    if (tid < KK * 6) ((double*)g_accum[b])[tid] = 0.0;
    if (b == 0 && tid >= 448 && tid < 448 + BB * 3) ((double*)g_colorsum)[tid - 448] = 0.0;
    if (tid < KK) {
        int i = tid >> 3, j = tid & 7;
        int y = 32 + 64 * i;
        int xc = 32 + 64 * j;
        const float* xb = x + (size_t)b * 3 * NPIX;
        float r  = xb[y * Ww + xc];
        float g  = xb[NPIX + y * Ww + xc];
        float bl = xb[2 * NPIX + y * Ww + xc];
        float fr = ratio_f();
        g_centers[b][tid][0] = r;
        g_centers[b][tid][1] = g;
        g_centers[b][tid][2] = bl;
        g_centers[b][tid][3] = __fmul_rn((float)y, fr);
        g_centers[b][tid][4] = __fmul_rn((float)xc, fr);
    }
}

// ---------------------------------------------------------------------------
// assign + accumulate segment sums.
// Block = 64x32 pixel tile; 1 thread = 4x2 pixel patch (16x16 patches).
// launch_bounds(256,3): ~80 regs -> 3 CTAs/SM = 24 warps (R10 had 16).
// Warp covers a COMPACT 32x8 px region -> fewer distinct labels per warp.
// Exact spatial pruning (labels bit-identical): candidate iff
//   spatialMin2_j <= min_j'(spatialMax2_j') + 3 (color slack) [+ fp pad]
// Candidates compacted ascending-j; +INF sentinel padding; fixed 16-candidate
// unrolled rounds.  d_j = ||c_j||^2 - 2 f.c_j  (f^2 dropped, argmin-safe)
//
// Reduction (R10-proven warp aggregation, tightened): per present slot, lanes
// form predicated partials; R,G,B via shfl tree; cnt/sumY/sumX as EXACT
// integers via hardware REDUX (__reduce_add_sync); lane 0 alone issues the
// global f64 atomics (L2-native, ~0.2M lane-ops/pass).
// ---------------------------------------------------------------------------
__global__ __launch_bounds__(256, 3) void assign_kernel(const float* __restrict__ x,
                                                        int storeLabels) {
    __shared__ float4 s_candA[64];            // {-2c0,-2c1,-2c2,-2c3}
    __shared__ float2 s_candB[64];            // {-2c4, ||c||^2 or +INF sentinel}
    __shared__ unsigned char s_jidx[64];
    __shared__ float s_smax[64];
    __shared__ unsigned int s_mask[2];
    __shared__ float s_T;

    int b   = blockIdx.y;
    int tid = threadIdx.x;
    int tileX = (blockIdx.x & 7) << 6;        // 8 x-tiles of 64
    int tileY = (blockIdx.x >> 3) << 5;       // 16 y-tiles of 32

    float fr = ratio_f();
    float byLo = __fmul_rn((float)tileY, fr);
    float byHi = __fmul_rn((float)(tileY + 31), fr);
    float bxLo = __fmul_rn((float)tileX, fr);
    float bxHi = __fmul_rn((float)(tileX + 63), fr);

    float c0 = 0.f, c1 = 0.f, c2 = 0.f, c3 = 0.f, c4 = 0.f, smin = 0.f;
    if (tid < 64) {
        s_candA[tid] = make_float4(0.f, 0.f, 0.f, 0.f);
        s_candB[tid] = make_float2(0.f, __int_as_float(0x7f800000));  // +INF
        s_jidx[tid] = 0;
        s_smax[tid] = 3.4e38f;
    }
    if (tid < KK) {
        c0 = g_centers[b][tid][0];
        c1 = g_centers[b][tid][1];
        c2 = g_centers[b][tid][2];
        c3 = g_centers[b][tid][3];
        c4 = g_centers[b][tid][4];
        float dyo = fmaxf(fmaxf(byLo - c3, c3 - byHi), 0.0f);
        float dxo = fmaxf(fmaxf(bxLo - c4, c4 - bxHi), 0.0f);
        smin = dyo * dyo + dxo * dxo;
        float dyM = fmaxf(fabsf(c3 - byLo), fabsf(c3 - byHi));
        float dxM = fmaxf(fabsf(c4 - bxLo), fabsf(c4 - bxHi));
        s_smax[tid] = dyM * dyM + dxM * dxM;
    }
    __syncthreads();
    if (tid < 32) {                        // warp-parallel min reduction
        float v = fminf(s_smax[tid], s_smax[tid + 32]);
#pragma unroll
        for (int off = 16; off > 0; off >>= 1)
            v = fminf(v, __shfl_xor_sync(0xffffffffu, v, off));
        if (tid == 0) s_T = v + 3.0f + 1e-3f;  // color slack + fp pad
    }
    __syncthreads();
    bool keep = (tid < KK) && (smin <= s_T);
    unsigned int wm = __ballot_sync(0xffffffffu, keep);
    if (tid < 64 && (tid & 31) == 0) s_mask[tid >> 5] = wm;
    __syncthreads();
    unsigned int m0 = s_mask[0], m1 = s_mask[1];
    if (keep) {
        unsigned int mm = (tid < 32) ? m0 : m1;
        int base = (tid < 32) ? 0 : __popc(m0);
        int pos = base + __popc(mm & ((1u << (tid & 31)) - 1u));
        float cc = __fmul_rn(c0, c0);
        cc = __fmaf_rn(c1, c1, cc);
        cc = __fmaf_rn(c2, c2, cc);
        cc = __fmaf_rn(c3, c3, cc);
        cc = __fmaf_rn(c4, c4, cc);
        s_candA[pos] = make_float4(__fmul_rn(-2.0f, c0), __fmul_rn(-2.0f, c1),
                                   __fmul_rn(-2.0f, c2), __fmul_rn(-2.0f, c3));
        s_candB[pos] = make_float2(__fmul_rn(-2.0f, c4), cc);
        s_jidx[pos] = (unsigned char)tid;
    }
    int C = __popc(m0) + __popc(m1);
    __syncthreads();

    // compact warp regions: warp covers 32x8 px (8 patch-cols x 4 patch-rows)
    int w    = tid >> 5;
    int lane = tid & 31;
    int patch_x = (lane & 7) | ((w & 1) << 3);   // 0..15
    int patch_y = (lane >> 3) | ((w >> 1) << 2); // 0..15
    int x0 = tileX + (patch_x << 2);
    int y0 = tileY + (patch_y << 1);

    const float* xr = x + (size_t)b * 3 * NPIX;
    const float* xg = xr + NPIX;
    const float* xb = xr + 2 * NPIX;

    float fxc[4], fy[2];
#pragma unroll
    for (int i = 0; i < 4; i++) fxc[i] = __fmul_rn((float)(x0 + i), fr);
#pragma unroll
    for (int i = 0; i < 2; i++) fy[i] = __fmul_rn((float)(y0 + i), fr);

    // load the 4x2 patch (3 channels)
    float4 Rr[2], Gr[2], Br[2];
#pragma unroll
    for (int r = 0; r < 2; r++) {
        Rr[r] = *(const float4*)(xr + (y0 + r) * Ww + x0);
        Gr[r] = *(const float4*)(xg + (y0 + r) * Ww + x0);
        Br[r] = *(const float4*)(xb + (y0 + r) * Ww + x0);
    }

    float dmin[8];
    int   lab[8];
#pragma unroll
    for (int p = 0; p < 8; p++) { dmin[p] = 3.4e38f; lab[p] = 0; }

    // fixed-trip unrolled rounds of 16 candidates (sentinel-padded, exact)
    int rounds = (C + 15) >> 4;            // 1 typically
    for (int rd = 0; rd < rounds; rd++) {
        int cbase = rd << 4;
#pragma unroll
        for (int i = 0; i < 16; i++) {
            int c = cbase + i;
            float4 cA = s_candA[c];
            float2 cB = s_candB[c];
            float e0 = __fmaf_rn(cA.w, fy[0], cB.y);
            float e1 = __fmaf_rn(cA.w, fy[1], cB.y);
#pragma unroll
            for (int r = 0; r < 2; r++) {
                float er = (r == 0) ? e0 : e1;
                const float* Rp = (const float*)&Rr[r];
                const float* Gp = (const float*)&Gr[r];
                const float* Bp = (const float*)&Br[r];
#pragma unroll
                for (int q = 0; q < 4; q++) {
                    float d = __fmaf_rn(cB.x, fxc[q], er);
                    d = __fmaf_rn(cA.x, Rp[q], d);
                    d = __fmaf_rn(cA.y, Gp[q], d);
                    d = __fmaf_rn(cA.z, Bp[q], d);
                    int p = r * 4 + q;
                    if (d < dmin[p]) { dmin[p] = d; lab[p] = c; }
                }
            }
        }
    }

    if (storeLabels) {
#pragma unroll
        for (int r = 0; r < 2; r++) {
            uchar4 L4 = make_uchar4(s_jidx[lab[r * 4 + 0]], s_jidx[lab[r * 4 + 1]],
                                    s_jidx[lab[r * 4 + 2]], s_jidx[lab[r * 4 + 3]]);
            *(uchar4*)&g_labels[b][(y0 + r) * Ww + x0] = L4;
        }
    }

    // ---- warp-aggregated reduction ----
    unsigned int pmLo = 0, pmHi = 0;
#pragma unroll
    for (int p = 0; p < 8; p++) {
        int l = lab[p];
        if (l < 32) pmLo |= (1u << l);
        else        pmHi |= (1u << (l - 32));
    }
    pmLo = __reduce_or_sync(0xffffffffu, pmLo);
    pmHi = __reduce_or_sync(0xffffffffu, pmHi);

    double* gacc = (double*)g_accum[b];
    double frd = (double)fr;

#pragma unroll 1
    for (int half = 0; half < 2; half++) {
        unsigned int m = (half == 0) ? pmLo : pmHi;
        int cofs = (half == 0) ? 0 : 32;
        while (m) {
            int c = __ffs(m) - 1;
            m &= (m - 1u);
            int slot = c + cofs;
            // predicated partials: floats for RGB, EXACT ints for cnt/Y/X
            float sR = 0.f, sG = 0.f, sB = 0.f;
            unsigned int icnt = 0, iy = 0, ix = 0;
#pragma unroll
            for (int p = 0; p < 8; p++) {
                int r = p >> 2, q = p & 3;
                bool hit = (lab[p] == slot);
                float mm = hit ? 1.0f : 0.0f;
                sR = __fmaf_rn(mm, ((const float*)&Rr[r])[q], sR);
                sG = __fmaf_rn(mm, ((const float*)&Gr[r])[q], sG);
                sB = __fmaf_rn(mm, ((const float*)&Br[r])[q], sB);
                if (hit) { icnt += 1u; iy += (unsigned)(y0 + r); ix += (unsigned)(x0 + q); }
            }
            // R,G,B: shfl tree (deterministic); cnt/Y/X: hardware REDUX
#pragma unroll
            for (int off = 16; off > 0; off >>= 1) {
                sR += __shfl_xor_sync(0xffffffffu, sR, off);
                sG += __shfl_xor_sync(0xffffffffu, sG, off);
                sB += __shfl_xor_sync(0xffffffffu, sB, off);
            }
            icnt = __reduce_add_sync(0xffffffffu, icnt);
            iy   = __reduce_add_sync(0xffffffffu, iy);
            ix   = __reduce_add_sync(0xffffffffu, ix);
            if (lane == 0 && icnt != 0u) {
                int jj = s_jidx[slot];
                atomicAdd(&gacc[jj * 6 + 0], (double)sR);
                atomicAdd(&gacc[jj * 6 + 1], (double)sG);
                atomicAdd(&gacc[jj * 6 + 2], (double)sB);
                atomicAdd(&gacc[jj * 6 + 3], frd * (double)iy);
                atomicAdd(&gacc[jj * 6 + 4], frd * (double)ix);
                atomicAdd(&gacc[jj * 6 + 5], (double)icnt);
            }
        }
    }
}

// ---------------------------------------------------------------------------
// centers <- sums / max(cnt,1); zero accumulator for next pass
// ---------------------------------------------------------------------------
__global__ void update_kernel() {
    int b = blockIdx.x;
    int k = threadIdx.x;
    if (k < KK) {
        double* a = g_accum[b][k];
        double cnt = a[5];
        double dv = cnt > 1.0 ? cnt : 1.0;
#pragma unroll
        for (int c = 0; c < 5; c++) {
            g_centers[b][k][c] = (float)(a[c] / dv);
            a[c] = 0.0;
        }
        a[5] = 0.0;
    }
}

// ---------------------------------------------------------------------------
// weighted color sum: w = 1/max(cnt,1) (fp32, like JAX); per-thread fp32
// partial (4 products), widened to double in the warp reduction + atomic
// ---------------------------------------------------------------------------
__global__ __launch_bounds__(256) void weight_kernel(const float* __restrict__ x) {
    __shared__ float s_inv[KK];
    int b   = blockIdx.y;
    int tid = threadIdx.x;
    if (tid < KK) {
        float cnt = (float)g_accum[b][tid][5];
        cnt = fmaxf(cnt, 1.0f);
        s_inv[tid] = __fdiv_rn(1.0f, cnt);
    }
    __syncthreads();

    int idx = (blockIdx.x * 256 + tid) * 4;
    const float* xr = x + (size_t)b * 3 * NPIX;
    const float* xg = xr + NPIX;
    const float* xb = xr + 2 * NPIX;
    float4 R  = *(const float4*)(xr + idx);
    float4 G  = *(const float4*)(xg + idx);
    float4 Bc = *(const float4*)(xb + idx);
    uchar4 L  = *(const uchar4*)&g_labels[b][idx];

    float w0 = s_inv[L.x], w1 = s_inv[L.y], w2 = s_inv[L.z], w3 = s_inv[L.w];
    float frt = __fadd_rn(__fadd_rn(__fmul_rn(R.x, w0), __fmul_rn(R.y, w1)),
                          __fadd_rn(__fmul_rn(R.z, w2), __fmul_rn(R.w, w3)));
    float fgt = __fadd_rn(__fadd_rn(__fmul_rn(G.x, w0), __fmul_rn(G.y, w1)),
                          __fadd_rn(__fmul_rn(G.z, w2), __fmul_rn(G.w, w3)));
    float fbt = __fadd_rn(__fadd_rn(__fmul_rn(Bc.x, w0), __fmul_rn(Bc.y, w1)),
                          __fadd_rn(__fmul_rn(Bc.z, w2), __fmul_rn(Bc.w, w3)));
    double sr = (double)frt, sg = (double)fgt, sb = (double)fbt;
#pragma unroll
    for (int off = 16; off > 0; off >>= 1) {
        sr += __shfl_down_sync(0xffffffffu, sr, off);
        sg += __shfl_down_sync(0xffffffffu, sg, off);
        sb += __shfl_down_sync(0xffffffffu, sb, off);
    }
    if ((tid & 31) == 0) {
        atomicAdd(&g_colorsum[b][0], sr);
        atomicAdd(&g_colorsum[b][1], sg);
        atomicAdd(&g_colorsum[b][2], sb);
    }
}

// ---------------------------------------------------------------------------
// finalize: fp32 epilogue mirroring the reference formula
// ---------------------------------------------------------------------------
__global__ void finalize_kernel(float* __restrict__ out) {
    int b = threadIdx.x;
    if (b < BB) {
        float mr = (float)(g_colorsum[b][0] / (double)NPIX);
        float mg = (float)(g_colorsum[b][1] / (double)NPIX);
        float mb = (float)(g_colorsum[b][2] / (double)NPIX);
        float drg = __fadd_rn(mr, -mg);
        float drb = __fadd_rn(mr, -mb);
        float dgb = __fadd_rn(mb, -mg);
        float Drg = __fmul_rn(drg, drg);
        float Drb = __fmul_rn(drb, drb);
        float Dgb = __fmul_rn(dgb, dgb);
        float t = __fadd_rn(__fadd_rn(__fmul_rn(Drg, Drg), __fmul_rn(Drb, Drb)),
                            __fmul_rn(Dgb, Dgb));
        out[b] = __fsqrt_rn(t);
    }
}

// ---------------------------------------------------------------------------
extern "C" void kernel_launch(void* const* d_in, const int* in_sizes, int n_in,
                              void* d_out, int out_size) {
    const float* x = (const float*)d_in[0];
    float* out = (float*)d_out;

    init_kernel<<<BB, 512>>>(x);
    for (int it = 0; it < SLIC_ITERS; it++) {
        assign_kernel<<<dim3(128, BB), 256>>>(x, 0);
        update_kernel<<<BB, 64>>>();
    }
    assign_kernel<<<dim3(128, BB), 256>>>(x, 1);      // final assign, store labels + counts
    weight_kernel<<<dim3(256, BB), 256>>>(x);
    finalize_kernel<<<1, 32>>>(out);
}

// round 12
// speedup vs baseline: 1.3671x; 1.3671x over previous
#include <cuda_runtime.h>
#include <math.h>

#define Hh 512
#define Ww 512
#define NPIX (512*512)
#define KK 50
#define BB 16
#define SLIC_ITERS 10
#define NSLAB (SLIC_ITERS + 2)     // 12: slab it = input of assign pass it

// scratch (static device arrays; no dynamic allocation allowed)
__device__ double        g_accum[NSLAB][BB][KK][6]; // [0..4]=feat sums, [5]=count
__device__ unsigned char g_labels[BB][NPIX];
__device__ double        g_colorsum[BB][3];

__device__ __forceinline__ float ratio_f() {
    return (float)(10.0 / sqrt((double)NPIX / (double)KK));
}

// ---------------------------------------------------------------------------
// init: zero ALL accumulator slabs, seed slab 0 with {feat, cnt=1} so that
// centers0 = feat/1 exactly (grid-initialized, first 50 of 8x8 grid)
// ---------------------------------------------------------------------------
__global__ void init_kernel(const float* __restrict__ x) {
    int b = blockIdx.x;
    int tid = threadIdx.x;
    // zero all slabs for this batch: NSLAB * KK * 6 doubles
    for (int i = tid; i < NSLAB * KK * 6; i += 512) {
        int slab = i / (KK * 6);
        int rem  = i - slab * (KK * 6);
        g_accum[slab][b][rem / 6][rem % 6] = 0.0;
    }
    if (b == 0 && tid >= 448 && tid < 448 + BB * 3) ((double*)g_colorsum)[tid - 448] = 0.0;
    __syncthreads();
    if (tid < KK) {
        int i = tid >> 3, j = tid & 7;
        int y = 32 + 64 * i;
        int xc = 32 + 64 * j;
        const float* xb = x + (size_t)b * 3 * NPIX;
        float r  = xb[y * Ww + xc];
        float g  = xb[NPIX + y * Ww + xc];
        float bl = xb[2 * NPIX + y * Ww + xc];
        float fr = ratio_f();
        double* a = g_accum[0][b][tid];
        a[0] = (double)r;
        a[1] = (double)g;
        a[2] = (double)bl;
        a[3] = (double)__fmul_rn((float)y, fr);
        a[4] = (double)__fmul_rn((float)xc, fr);
        a[5] = 1.0;
    }
}

// ---------------------------------------------------------------------------
// assign pass it: centers computed IN-PROLOGUE from g_accum[it] (fp32 divide,
// like JAX's sums/max(cnts,1)); segment sums atomically added to g_accum[it+1].
// Block = 64x32 pixel tile; 1 thread = 4x2 pixel patch; warp covers 32x8 px.
// Exact spatial pruning (labels bit-identical): candidate iff
//   spatialMin2_j <= min_j'(spatialMax2_j') + 3 (color slack) [+ fp pad]
// Candidates compacted ascending-j; +INF sentinel padding; fixed 8-candidate
// unrolled rounds (16 wasted ~half the FMAs on sentinels at typical C=6-10).
// d_j = ||c_j||^2 - 2 f.c_j  (f^2 dropped, argmin-safe)
// Reduction: R10-proven warp aggregation; RGB via shfl tree, cnt/Y/X exact
// integers via REDUX; lane 0 alone issues global f64 atomics.
// ---------------------------------------------------------------------------
__global__ __launch_bounds__(256, 3) void assign_kernel(const float* __restrict__ x,
                                                        int it, int storeLabels) {
    __shared__ float4 s_candA[64];            // {-2c0,-2c1,-2c2,-2c3}
    __shared__ float2 s_candB[64];            // {-2c4, ||c||^2 or +INF sentinel}
    __shared__ unsigned char s_jidx[64];
    __shared__ float s_smax[64];
    __shared__ unsigned int s_mask[2];
    __shared__ float s_T;

    int b   = blockIdx.y;
    int tid = threadIdx.x;
    int tileX = (blockIdx.x & 7) << 6;        // 8 x-tiles of 64
    int tileY = (blockIdx.x >> 3) << 5;       // 16 y-tiles of 32

    float fr = ratio_f();
    float byLo = __fmul_rn((float)tileY, fr);
    float byHi = __fmul_rn((float)(tileY + 31), fr);
    float bxLo = __fmul_rn((float)tileX, fr);
    float bxHi = __fmul_rn((float)(tileX + 63), fr);

    float c0 = 0.f, c1 = 0.f, c2 = 0.f, c3 = 0.f, c4 = 0.f, smin = 0.f;
    if (tid < 64) {
        s_candA[tid] = make_float4(0.f, 0.f, 0.f, 0.f);
        s_candB[tid] = make_float2(0.f, __int_as_float(0x7f800000));  // +INF
        s_jidx[tid] = 0;
        s_smax[tid] = 3.4e38f;
    }
    if (tid < KK) {
        // centers from previous pass's sums (fused update, JAX-style fp32 div)
        const double* a = g_accum[it][b][tid];
        float fcnt = fmaxf((float)a[5], 1.0f);
        c0 = __fdiv_rn((float)a[0], fcnt);
        c1 = __fdiv_rn((float)a[1], fcnt);
        c2 = __fdiv_rn((float)a[2], fcnt);
        c3 = __fdiv_rn((float)a[3], fcnt);
        c4 = __fdiv_rn((float)a[4], fcnt);
        float dyo = fmaxf(fmaxf(byLo - c3, c3 - byHi), 0.0f);
        float dxo = fmaxf(fmaxf(bxLo - c4, c4 - bxHi), 0.0f);
        smin = dyo * dyo + dxo * dxo;
        float dyM = fmaxf(fabsf(c3 - byLo), fabsf(c3 - byHi));
        float dxM = fmaxf(fabsf(c4 - bxLo), fabsf(c4 - bxHi));
        s_smax[tid] = dyM * dyM + dxM * dxM;
    }
    __syncthreads();
    if (tid < 32) {                        // warp-parallel min reduction
        float v = fminf(s_smax[tid], s_smax[tid + 32]);
#pragma unroll
        for (int off = 16; off > 0; off >>= 1)
            v = fminf(v, __shfl_xor_sync(0xffffffffu, v, off));
        if (tid == 0) s_T = v + 3.0f + 1e-3f;  // color slack + fp pad
    }
    __syncthreads();
    bool keep = (tid < KK) && (smin <= s_T);
    unsigned int wm = __ballot_sync(0xffffffffu, keep);
    if (tid < 64 && (tid & 31) == 0) s_mask[tid >> 5] = wm;
    __syncthreads();
    unsigned int m0 = s_mask[0], m1 = s_mask[1];
    if (keep) {
        unsigned int mm = (tid < 32) ? m0 : m1;
        int base = (tid < 32) ? 0 : __popc(m0);
        int pos = base + __popc(mm & ((1u << (tid & 31)) - 1u));
        float cc = __fmul_rn(c0, c0);
        cc = __fmaf_rn(c1, c1, cc);
        cc = __fmaf_rn(c2, c2, cc);
        cc = __fmaf_rn(c3, c3, cc);
        cc = __fmaf_rn(c4, c4, cc);
        s_candA[pos] = make_float4(__fmul_rn(-2.0f, c0), __fmul_rn(-2.0f, c1),
                                   __fmul_rn(-2.0f, c2), __fmul_rn(-2.0f, c3));
        s_candB[pos] = make_float2(__fmul_rn(-2.0f, c4), cc);
        s_jidx[pos] = (unsigned char)tid;
    }
    int C = __popc(m0) + __popc(m1);
    __syncthreads();

    // compact warp regions: warp covers 32x8 px (8 patch-cols x 4 patch-rows)
    int w    = tid >> 5;
    int lane = tid & 31;
    int patch_x = (lane & 7) | ((w & 1) << 3);   // 0..15
    int patch_y = (lane >> 3) | ((w >> 1) << 2); // 0..15
    int x0 = tileX + (patch_x << 2);
    int y0 = tileY + (patch_y << 1);

    const float* xr = x + (size_t)b * 3 * NPIX;
    const float* xg = xr + NPIX;
    const float* xb = xr + 2 * NPIX;

    float fxc[4], fy[2];
#pragma unroll
    for (int i = 0; i < 4; i++) fxc[i] = __fmul_rn((float)(x0 + i), fr);
#pragma unroll
    for (int i = 0; i < 2; i++) fy[i] = __fmul_rn((float)(y0 + i), fr);

    // load the 4x2 patch (3 channels)
    float4 Rr[2], Gr[2], Br[2];
#pragma unroll
    for (int r = 0; r < 2; r++) {
        Rr[r] = *(const float4*)(xr + (y0 + r) * Ww + x0);
        Gr[r] = *(const float4*)(xg + (y0 + r) * Ww + x0);
        Br[r] = *(const float4*)(xb + (y0 + r) * Ww + x0);
    }

    float dmin[8];
    int   lab[8];
#pragma unroll
    for (int p = 0; p < 8; p++) { dmin[p] = 3.4e38f; lab[p] = 0; }

    // fixed-trip unrolled rounds of 8 candidates (sentinel-padded, exact)
    int rounds = (C + 7) >> 3;             // 1-2 typically
    for (int rd = 0; rd < rounds; rd++) {
        int cbase = rd << 3;
#pragma unroll
        for (int i = 0; i < 8; i++) {
            int c = cbase + i;
            float4 cA = s_candA[c];
            float2 cB = s_candB[c];
            float e0 = __fmaf_rn(cA.w, fy[0], cB.y);
            float e1 = __fmaf_rn(cA.w, fy[1], cB.y);
#pragma unroll
            for (int r = 0; r < 2; r++) {
                float er = (r == 0) ? e0 : e1;
                const float* Rp = (const float*)&Rr[r];
                const float* Gp = (const float*)&Gr[r];
                const float* Bp = (const float*)&Br[r];
#pragma unroll
                for (int q = 0; q < 4; q++) {
                    float d = __fmaf_rn(cB.x, fxc[q], er);
                    d = __fmaf_rn(cA.x, Rp[q], d);
                    d = __fmaf_rn(cA.y, Gp[q], d);
                    d = __fmaf_rn(cA.z, Bp[q], d);
                    int p = r * 4 + q;
                    if (d < dmin[p]) { dmin[p] = d; lab[p] = c; }
                }
            }
        }
    }

    if (storeLabels) {
#pragma unroll
        for (int r = 0; r < 2; r++) {
            uchar4 L4 = make_uchar4(s_jidx[lab[r * 4 + 0]], s_jidx[lab[r * 4 + 1]],
                                    s_jidx[lab[r * 4 + 2]], s_jidx[lab[r * 4 + 3]]);
            *(uchar4*)&g_labels[b][(y0 + r) * Ww + x0] = L4;
        }
    }

    // ---- warp-aggregated reduction ----
    unsigned int pmLo = 0, pmHi = 0;
#pragma unroll
    for (int p = 0; p < 8; p++) {
        int l = lab[p];
        if (l < 32) pmLo |= (1u << l);
        else        pmHi |= (1u << (l - 32));
    }
    pmLo = __reduce_or_sync(0xffffffffu, pmLo);
    pmHi = __reduce_or_sync(0xffffffffu, pmHi);

    double* gacc = (double*)g_accum[it + 1][b];
    double frd = (double)fr;

#pragma unroll 1
    for (int half = 0; half < 2; half++) {
        unsigned int m = (half == 0) ? pmLo : pmHi;
        int cofs = (half == 0) ? 0 : 32;
        while (m) {
            int c = __ffs(m) - 1;
            m &= (m - 1u);
            int slot = c + cofs;
            // predicated partials: floats for RGB, EXACT ints for cnt/Y/X
            float sR = 0.f, sG = 0.f, sB = 0.f;
            unsigned int icnt = 0, iy = 0, ix = 0;
#pragma unroll
            for (int p = 0; p < 8; p++) {
                int r = p >> 2, q = p & 3;
                bool hit = (lab[p] == slot);
                float mm = hit ? 1.0f : 0.0f;
                sR = __fmaf_rn(mm, ((const float*)&Rr[r])[q], sR);
                sG = __fmaf_rn(mm, ((const float*)&Gr[r])[q], sG);
                sB = __fmaf_rn(mm, ((const float*)&Br[r])[q], sB);
                if (hit) { icnt += 1u; iy += (unsigned)(y0 + r); ix += (unsigned)(x0 + q); }
            }
            // R,G,B: shfl tree (deterministic); cnt/Y/X: hardware REDUX
#pragma unroll
            for (int off = 16; off > 0; off >>= 1) {
                sR += __shfl_xor_sync(0xffffffffu, sR, off);
                sG += __shfl_xor_sync(0xffffffffu, sG, off);
                sB += __shfl_xor_sync(0xffffffffu, sB, off);
            }
            icnt = __reduce_add_sync(0xffffffffu, icnt);
            iy   = __reduce_add_sync(0xffffffffu, iy);
            ix   = __reduce_add_sync(0xffffffffu, ix);
            if (lane == 0 && icnt != 0u) {
                int jj = s_jidx[slot];
                atomicAdd(&gacc[jj * 6 + 0], (double)sR);
                atomicAdd(&gacc[jj * 6 + 1], (double)sG);
                atomicAdd(&gacc[jj * 6 + 2], (double)sB);
                atomicAdd(&gacc[jj * 6 + 3], frd * (double)iy);
                atomicAdd(&gacc[jj * 6 + 4], frd * (double)ix);
                atomicAdd(&gacc[jj * 6 + 5], (double)icnt);
            }
        }
    }
}

// ---------------------------------------------------------------------------
// weighted color sum: w = 1/max(cnt,1) (fp32, like JAX); per-thread fp32
// partial (4 products), widened to double in the warp reduction + atomic.
// Counts come from the final assign pass's slab (SLIC_ITERS+1).
// ---------------------------------------------------------------------------
__global__ __launch_bounds__(256) void weight_kernel(const float* __restrict__ x) {
    __shared__ float s_inv[KK];
    int b   = blockIdx.y;
    int tid = threadIdx.x;
    if (tid < KK) {
        float cnt = (float)g_accum[SLIC_ITERS + 1][b][tid][5];
        cnt = fmaxf(cnt, 1.0f);
        s_inv[tid] = __fdiv_rn(1.0f, cnt);
    }
    __syncthreads();

    int idx = (blockIdx.x * 256 + tid) * 4;
    const float* xr = x + (size_t)b * 3 * NPIX;
    const float* xg = xr + NPIX;
    const float* xb = xr + 2 * NPIX;
    float4 R  = *(const float4*)(xr + idx);
    float4 G  = *(const float4*)(xg + idx);
    float4 Bc = *(const float4*)(xb + idx);
    uchar4 L  = *(const uchar4*)&g_labels[b][idx];

    float w0 = s_inv[L.x], w1 = s_inv[L.y], w2 = s_inv[L.z], w3 = s_inv[L.w];
    float frt = __fadd_rn(__fadd_rn(__fmul_rn(R.x, w0), __fmul_rn(R.y, w1)),
                          __fadd_rn(__fmul_rn(R.z, w2), __fmul_rn(R.w, w3)));
    float fgt = __fadd_rn(__fadd_rn(__fmul_rn(G.x, w0), __fmul_rn(G.y, w1)),
                          __fadd_rn(__fmul_rn(G.z, w2), __fmul_rn(G.w, w3)));
    float fbt = __fadd_rn(__fadd_rn(__fmul_rn(Bc.x, w0), __fmul_rn(Bc.y, w1)),
                          __fadd_rn(__fmul_rn(Bc.z, w2), __fmul_rn(Bc.w, w3)));
    double sr = (double)frt, sg = (double)fgt, sb = (double)fbt;
#pragma unroll
    for (int off = 16; off > 0; off >>= 1) {
        sr += __shfl_down_sync(0xffffffffu, sr, off);
        sg += __shfl_down_sync(0xffffffffu, sg, off);
        sb += __shfl_down_sync(0xffffffffu, sb, off);
    }
    if ((tid & 31) == 0) {
        atomicAdd(&g_colorsum[b][0], sr);
        atomicAdd(&g_colorsum[b][1], sg);
        atomicAdd(&g_colorsum[b][2], sb);
    }
}

// ---------------------------------------------------------------------------
// finalize: fp32 epilogue mirroring the reference formula
// ---------------------------------------------------------------------------
__global__ void finalize_kernel(float* __restrict__ out) {
    int b = threadIdx.x;
    if (b < BB) {
        float mr = (float)(g_colorsum[b][0] / (double)NPIX);
        float mg = (float)(g_colorsum[b][1] / (double)NPIX);
        float mb = (float)(g_colorsum[b][2] / (double)NPIX);
        float drg = __fadd_rn(mr, -mg);
        float drb = __fadd_rn(mr, -mb);
        float dgb = __fadd_rn(mb, -mg);
        float Drg = __fmul_rn(drg, drg);
        float Drb = __fmul_rn(drb, drb);
        float Dgb = __fmul_rn(dgb, dgb);
        float t = __fadd_rn(__fadd_rn(__fmul_rn(Drg, Drg), __fmul_rn(Drb, Drb)),
                            __fmul_rn(Dgb, Dgb));
        out[b] = __fsqrt_rn(t);
    }
}

// ---------------------------------------------------------------------------
extern "C" void kernel_launch(void* const* d_in, const int* in_sizes, int n_in,
                              void* d_out, int out_size) {
    const float* x = (const float*)d_in[0];
    float* out = (float*)d_out;

    init_kernel<<<BB, 512>>>(x);
    for (int it = 0; it < SLIC_ITERS; it++)
        assign_kernel<<<dim3(128, BB), 256>>>(x, it, 0);
    assign_kernel<<<dim3(128, BB), 256>>>(x, SLIC_ITERS, 1);  // final: labels+counts
    weight_kernel<<<dim3(256, BB), 256>>>(x);
    finalize_kernel<<<1, 32>>>(out);
}